// round 2
// baseline (speedup 1.0000x reference)
#include <cuda_runtime.h>
#include <cuda_bf16.h>
#include <cstdint>

#define NSTATES 256
#define DDIM    128
#define BATCH   64
#define TLEN    512
#define BT      (BATCH * TLEN)
#define LOG2PI_F 1.8378770664093453f

// ---------------- device scratch (no allocations allowed) ----------------
__device__ __align__(16) float   g_E[BT * NSTATES];              // 32 MB emissions
__device__ __align__(16) __nv_bfloat16 g_Acm[NSTATES * NSTATES]; // softmax(A), COLUMN-major: g_Acm[j*256 + i]
__device__ __align__(16) float   g_logpi[NSTATES];
__device__ __align__(16) float   g_ivT[DDIM * NSTATES];          // ivT[d*256+n] = exp(-log_var[n][d])
__device__ __align__(16) float   g_mivT[DDIM * NSTATES];         // mu*iv, transposed
__device__ __align__(16) float   g_cn[NSTATES];                  // sum_d (mu^2*iv + log_var + log2pi)

// expand bf16x2 word -> f32x2 pair and fused-multiply-add with packed p pair
#define BFMA(acc, w, pp)                                  \
    asm("{\n\t"                                           \
        ".reg .b32 lo, hi;\n\t"                           \
        ".reg .b64 av;\n\t"                               \
        "prmt.b32 lo, %1, %3, 0x1044;\n\t"                \
        "prmt.b32 hi, %1, %3, 0x3244;\n\t"                \
        "mov.b64 av, {lo, hi};\n\t"                       \
        "fma.rn.f32x2 %0, av, %2, %0;\n\t"                \
        "}" : "+l"(acc) : "r"(w), "l"(pp), "r"(0u))

static __device__ __forceinline__ float pairsum(unsigned long long v) {
    return __uint_as_float((unsigned)v) + __uint_as_float((unsigned)(v >> 32));
}

// ---------------- prep 1: per-(n) param transforms ----------------
__global__ void k_prep_params(const float* __restrict__ mu,
                              const float* __restrict__ log_var) {
    int n = blockIdx.x;
    int d = threadIdx.x;
    float lv = log_var[n * DDIM + d];
    float iv = __expf(-lv);
    float mv = mu[n * DDIM + d];
    g_ivT [d * NSTATES + n] = iv;
    g_mivT[d * NSTATES + n] = mv * iv;

    float c = fmaf(mv * mv, iv, lv + LOG2PI_F);
    #pragma unroll
    for (int o = 16; o; o >>= 1) c += __shfl_xor_sync(0xffffffffu, c, o);
    __shared__ float red[4];
    if ((d & 31) == 0) red[d >> 5] = c;
    __syncthreads();
    if (d == 0) g_cn[n] = red[0] + red[1] + red[2] + red[3];
}

// ---------------- prep 2: softmax of transition rows + log_softmax priors ----------------
__global__ void k_prep_trans(const float* __restrict__ trans,
                             const float* __restrict__ priors,
                             float* __restrict__ out) {
    __shared__ float red[8];
    int tid = threadIdx.x;
    int blk = blockIdx.x;

    float v = (blk < NSTATES) ? trans[blk * NSTATES + tid] : priors[tid];

    float w = v;
    #pragma unroll
    for (int o = 16; o; o >>= 1) w = fmaxf(w, __shfl_xor_sync(0xffffffffu, w, o));
    if ((tid & 31) == 0) red[tid >> 5] = w;
    __syncthreads();
    float m = red[0];
    #pragma unroll
    for (int q = 1; q < 8; q++) m = fmaxf(m, red[q]);
    __syncthreads();

    float ex = __expf(v - m);
    float s = ex;
    #pragma unroll
    for (int o = 16; o; o >>= 1) s += __shfl_xor_sync(0xffffffffu, s, o);
    if ((tid & 31) == 0) red[tid >> 5] = s;
    __syncthreads();
    float S = 0.f;
    #pragma unroll
    for (int q = 0; q < 8; q++) S += red[q];

    if (blk < NSTATES) {
        g_Acm[tid * NSTATES + blk] = __float2bfloat16(ex / S);
    } else {
        g_logpi[tid] = v - m - __logf(S);
        if (tid == 0) out[0] = 0.0f;   // re-zeroed on every (graph) replay
    }
}

// ---------------- emission kernel (unchanged) ----------------
__global__ void __launch_bounds__(256) k_emission(const float* __restrict__ X) {
    __shared__ float xT[DDIM * 68];
    int tid = threadIdx.x;
    int bt0 = blockIdx.x * 64;

    for (int idx = tid; idx < 64 * DDIM; idx += 256) {
        int btl = idx >> 7, d = idx & 127;
        xT[d * 68 + btl] = X[(bt0 + btl) * DDIM + d];
    }
    __syncthreads();

    int ng  = tid & 15;
    int btg = tid >> 4;

    float acc[64];
    #pragma unroll
    for (int q = 0; q < 64; q++) acc[q] = 0.f;

    for (int d = 0; d < DDIM; d++) {
        float4 xv = *(const float4*)(xT + d * 68 + 4 * btg);
        float xs[4] = {xv.x, xv.y, xv.z, xv.w};
        const float4* ivp = (const float4*)(g_ivT  + d * NSTATES + 16 * ng);
        const float4* mvp = (const float4*)(g_mivT + d * NSTATES + 16 * ng);
        float4 ivv[4], mvv[4];
        #pragma unroll
        for (int c = 0; c < 4; c++) { ivv[c] = ivp[c]; mvv[c] = mvp[c]; }

        #pragma unroll
        for (int q = 0; q < 4; q++) {
            float x = xs[q];
            float z = -0.5f * x;
            #pragma unroll
            for (int c = 0; c < 4; c++) {
                acc[q*16 + c*4 + 0] = fmaf(x, fmaf(z, ivv[c].x, mvv[c].x), acc[q*16 + c*4 + 0]);
                acc[q*16 + c*4 + 1] = fmaf(x, fmaf(z, ivv[c].y, mvv[c].y), acc[q*16 + c*4 + 1]);
                acc[q*16 + c*4 + 2] = fmaf(x, fmaf(z, ivv[c].z, mvv[c].z), acc[q*16 + c*4 + 2]);
                acc[q*16 + c*4 + 3] = fmaf(x, fmaf(z, ivv[c].w, mvv[c].w), acc[q*16 + c*4 + 3]);
            }
        }
    }

    #pragma unroll
    for (int q = 0; q < 4; q++) {
        int bt = bt0 + 4 * btg + q;
        #pragma unroll
        for (int c = 0; c < 4; c++) {
            float4 cn4 = ((const float4*)(g_cn + 16 * ng))[c];
            float4 o;
            o.x = fmaf(-0.5f, cn4.x, acc[q*16 + c*4 + 0]);
            o.y = fmaf(-0.5f, cn4.y, acc[q*16 + c*4 + 1]);
            o.z = fmaf(-0.5f, cn4.z, acc[q*16 + c*4 + 2]);
            o.w = fmaf(-0.5f, cn4.w, acc[q*16 + c*4 + 3]);
            ((float4*)(g_E + (size_t)bt * NSTATES + 16 * ng))[c] = o;
        }
    }
}

// ---------------- forward recursion ----------------
// 64 CTAs (one per batch), 512 threads. Column j = tid&255, half = tid>>8.
// Each thread accumulates 128 of the 256 i-terms of column j; halves combined in smem.
// A bf16 col-major in smem, column stride 132 words (16B-aligned, conflict-free LDS.128).
#define A_STRIDE 132
#define FWD_SMEM (NSTATES*A_STRIDE*4 + 256*4 + 512*4 + 8*4)

__global__ void __launch_bounds__(512) k_forward(float* __restrict__ out) {
    extern __shared__ unsigned char sm[];
    uint32_t* Asm  = (uint32_t*)sm;                           // [j*132 + k], word k = bf16x2 (A[2k][j], A[2k+1][j])
    float*    p    = (float*)(sm + NSTATES * A_STRIDE * 4);   // 256 probs
    float*    ps   = p + 256;                                 // 512 partial sums
    float*    wred = ps + 512;                                // 8 warp-reduction slots

    int b    = blockIdx.x;
    int tid  = threadIdx.x;
    int j    = tid & 255;
    int half = tid >> 8;

    // load A tile into padded smem
    const uint32_t* Ag = (const uint32_t*)g_Acm;
    for (int idx = tid; idx < 256 * 128; idx += 512) {
        int jj = idx >> 7, k = idx & 127;
        Asm[jj * A_STRIDE + k] = Ag[idx];
    }

    // alpha0 = log_pi + E[b,0,:]   (held by tid<256)
    float a = 0.f;
    if (tid < 256)
        a = g_logpi[j] + g_E[(size_t)b * TLEN * NSTATES + j];

    const uint4*  acol  = (const uint4*)(Asm + j * A_STRIDE + half * 64);
    const float*  pbase = p + half * 128;

    for (int t = 1; t < TLEN; t++) {
        // ---- phase 1: m = max_i alpha_i (warps 0-7 only) ----
        if (tid < 256) {
            float v = a;
            #pragma unroll
            for (int o = 16; o; o >>= 1) v = fmaxf(v, __shfl_xor_sync(0xffffffffu, v, o));
            if ((tid & 31) == 0) wred[tid >> 5] = v;
        }
        __syncthreads();                                   // bar A

        float m = 0.f, e = 0.f;
        if (tid < 256) {
            m = wred[0];
            #pragma unroll
            for (int q = 1; q < 8; q++) m = fmaxf(m, wred[q]);
            p[j] = __expf(a - m);
            e = g_E[((size_t)b * TLEN + t) * NSTATES + j]; // prefetch, consumed after bar C
        }
        __syncthreads();                                   // bar B

        // ---- phase 2: partial dot s_j(half) = sum over 128 i-terms ----
        unsigned long long acc0 = 0ull, acc1 = 0ull, acc2 = 0ull, acc3 = 0ull;
        #pragma unroll
        for (int it = 0; it < 16; it++) {
            uint4 aw = acol[it];                                          // words k0..k0+3
            ulonglong2 pv0 = *(const ulonglong2*)(pbase + 8 * it);        // pairs k0, k0+1
            ulonglong2 pv1 = *(const ulonglong2*)(pbase + 8 * it + 4);    // pairs k0+2, k0+3
            BFMA(acc0, aw.x, pv0.x);
            BFMA(acc1, aw.y, pv0.y);
            BFMA(acc2, aw.z, pv1.x);
            BFMA(acc3, aw.w, pv1.y);
        }
        ps[tid] = (pairsum(acc0) + pairsum(acc1)) + (pairsum(acc2) + pairsum(acc3));
        __syncthreads();                                   // bar C

        if (tid < 256)
            a = e + m + __logf(ps[j] + ps[j + 256]);
    }

    // ---- final logsumexp over states, accumulate into out ----
    if (tid < 256) {
        float v = a;
        #pragma unroll
        for (int o = 16; o; o >>= 1) v = fmaxf(v, __shfl_xor_sync(0xffffffffu, v, o));
        if ((tid & 31) == 0) wred[tid >> 5] = v;
    }
    __syncthreads();
    float m = 0.f, s = 0.f;
    if (tid < 256) {
        m = wred[0];
        #pragma unroll
        for (int q = 1; q < 8; q++) m = fmaxf(m, wred[q]);
        s = __expf(a - m);
        #pragma unroll
        for (int o = 16; o; o >>= 1) s += __shfl_xor_sync(0xffffffffu, s, o);
    }
    __syncthreads();                                       // protect wred rewrite
    if (tid < 256 && (tid & 31) == 0) wred[tid >> 5] = s;
    __syncthreads();
    if (tid == 0) {
        float S = 0.f;
        #pragma unroll
        for (int q = 0; q < 8; q++) S += wred[q];
        atomicAdd(out, m + __logf(S));
    }
}

// ---------------- launch ----------------
extern "C" void kernel_launch(void* const* d_in, const int* in_sizes, int n_in,
                              void* d_out, int out_size) {
    const float* X       = (const float*)d_in[0];  // [64,512,128]
    const float* mu      = (const float*)d_in[1];  // [256,128]
    const float* log_var = (const float*)d_in[2];  // [256,128]
    const float* trans   = (const float*)d_in[3];  // [256,256]
    const float* priors  = (const float*)d_in[4];  // [256]
    float* out = (float*)d_out;

    cudaFuncSetAttribute(k_forward, cudaFuncAttributeMaxDynamicSharedMemorySize, FWD_SMEM);

    k_prep_params<<<NSTATES, DDIM>>>(mu, log_var);
    k_prep_trans <<<NSTATES + 1, NSTATES>>>(trans, priors, out);
    k_emission   <<<BT / 64, 256>>>(X);
    k_forward    <<<BATCH, 512, FWD_SMEM>>>(out);
}